// round 10
// baseline (speedup 1.0000x reference)
#include <cuda_runtime.h>

// Problem constants
#define N_B    64
#define T_T    2048
#define IN_P   8
#define C_C    2
#define M_M    10
#define NSTEP  2047            // number of increments (T-1)
#define LSEG   8               // steps per segment
#define SSEG   256             // segments per chain
#define NCHAIN 128             // N*C
#define NU1    (NCHAIN * SSEG) // 32768 segment units
#define GRP    16
#define NU2    (NCHAIN * (SSEG / GRP)) // 2048
#define NU3    NCHAIN                  // 128

#define CS 12                  // smem column stride (floats), 48B -> LDS.128-aligned
#define MS 132                 // smem matrix stride; 132 % 32 == 4 -> conflict-free across 6 groups
#define WS (6 * MS)            // per-warp tile stride (792 floats)
#define NWARP 4                // warps per block (128 threads)

// Scratch (static device arrays; allocation-free)
__device__ float g_part1[NU1 * 100]; // [unit][col][row], col-major per matrix
__device__ float g_part2[NU2 * 100];

// acc = S @ W : S is 10x10 col-major (stride CS) in shared; W = lane's 2 columns.
// 5 lanes of a group read the same address -> broadcast; groups land on
// disjoint bank quads (MS%32==4). 30 LDS insts per matmul.
__device__ __forceinline__ void mm10s(const float* __restrict__ S,
                                      const float W[2][10], float acc[2][10])
{
#pragma unroll
    for (int j = 0; j < 2; ++j)
#pragma unroll
        for (int r = 0; r < 10; ++r) acc[j][r] = 0.f;
#pragma unroll
    for (int m = 0; m < 10; ++m) {
        const float* col = S + m * CS;
        float4 v0 = *(const float4*)(col);
        float4 v1 = *(const float4*)(col + 4);
        float2 v2 = *(const float2*)(col + 8);
        float cv[10] = {v0.x, v0.y, v0.z, v0.w, v1.x, v1.y, v1.z, v1.w, v2.x, v2.y};
        float w0 = W[0][m], w1 = W[1][m];
#pragma unroll
        for (int r = 0; r < 10; ++r) acc[0][r] = fmaf(cv[r], w0, acc[0][r]);
#pragma unroll
        for (int r = 0; r < 10; ++r) acc[1][r] = fmaf(cv[r], w1, acc[1][r]);
    }
}

// Store lane's 2 columns into a broadcast tile (6 STS insts).
__device__ __forceinline__ void store_cols(float* __restrict__ S,
                                           const float V[2][10], int j0)
{
#pragma unroll
    for (int j = 0; j < 2; ++j) {
        float* p = S + (j0 + j) * CS;
        *(float4*)(p)     = make_float4(V[j][0], V[j][1], V[j][2], V[j][3]);
        *(float4*)(p + 4) = make_float4(V[j][4], V[j][5], V[j][6], V[j][7]);
        *(float2*)(p + 8) = make_float2(V[j][8], V[j][9]);
    }
}

// Kernel 1: per-(chain,segment) ordered product of expm(G_t), LSEG steps.
// exp(G): Paterson-Stockmeyer Horner-in-G^2, Taylor degree 7 (5 matmuls/step).
// Register budget 102 (5 CTAs/SM): P in registers; G parked in tile Tg
// (matmul left-op + own-column elementwise reads); G2 in tile Tg2.
__global__ void __launch_bounds__(128, 5)
seg_kernel(const float* __restrict__ x, const float* __restrict__ A)
{
    // skew repacked: skp[((c*8+i)*5+q)*20 + m*2 + jj] = skew[c][i][m][2q+jj]
    __shared__ __align__(16) float skp[1600];
    __shared__ __align__(16) float tg [NWARP * WS]; // G tile (later holds P)
    __shared__ __align__(16) float tg2[NWARP * WS]; // G2 tile

    for (int idx = threadIdx.x; idx < 1600; idx += 128) {
        int jj = idx & 1;
        int m  = (idx >> 1) % 10;
        int qq = (idx / 20) % 5;
        int i  = (idx / 100) % 8;
        int c  = idx / 800;
        int col = 2 * qq + jj;
        skp[idx] = A[((c * 8 + i) * 10 + m) * 10 + col]
                 - A[((c * 8 + i) * 10 + col) * 10 + m];
    }
    __syncthreads();

    int lane  = threadIdx.x & 31;
    int warpG = (blockIdx.x * blockDim.x + threadIdx.x) >> 5;
    int warpL = threadIdx.x >> 5;
    int g = lane / 5; if (g > 5) g = 5;      // lanes 30,31 shadow group 5
    int q = lane - g * 5; if (q > 4) q = 4;  // duplicate cols 8,9 (benign)
    int unitRaw = warpG * 6 + g;
    int unit = (unitRaw < NU1) ? unitRaw : (NU1 - 1);
    bool active = (lane < 30) && (unitRaw < NU1);
    int chain = unit / SSEG;
    int seg   = unit % SSEG;
    int n = chain >> 1;
    int c = chain & 1;
    int j0 = q * 2;
    float* Tg  = tg  + warpL * WS + g * MS;
    float* Tg2 = tg2 + warpL * WS + g * MS;
    const float* skb = skp + (c * 40 + q) * 20;

    const float4* X4 = (const float4*)x;
    int t0 = seg * LSEG;
    int rb = (n * T_T + t0) * 2;
    float4 xa = X4[rb], xb = X4[rb + 1];

    float P[2][10];
#pragma unroll
    for (int j = 0; j < 2; ++j)
#pragma unroll
        for (int r = 0; r < 10; ++r) P[j][r] = (r == j0 + j) ? 1.f : 0.f;

    const float a0 = 1.f, a1 = 1.f, a2 = 0.5f, a3 = 1.f/6.f,
                a4 = 1.f/24.f, a5 = 1.f/120.f, a6 = 1.f/720.f, a7 = 1.f/5040.f;

#pragma unroll 1
    for (int s = 0; s < LSEG; ++s) {
        int t = t0 + s;
        int tn = (t < NSTEP) ? (t + 1) : t; // tail: tn==t -> dx=0 -> E=I
        int rn = (n * T_T + tn) * 2;
        float4 ya = X4[rn], yb = X4[rn + 1];
        float dx[8];
        dx[0] = ya.x - xa.x; dx[1] = ya.y - xa.y; dx[2] = ya.z - xa.z; dx[3] = ya.w - xa.w;
        dx[4] = yb.x - xb.x; dx[5] = yb.y - xb.y; dx[6] = yb.z - xb.z; dx[7] = yb.w - xb.w;
        xa = ya; xb = yb;

        // G columns via vectorized skew reads
        float G[2][10];
#pragma unroll
        for (int j = 0; j < 2; ++j)
#pragma unroll
            for (int r = 0; r < 10; ++r) G[j][r] = 0.f;
#pragma unroll
        for (int i = 0; i < 8; ++i) {
            const float4* p = (const float4*)(skb + i * 100);
            float d = dx[i];
#pragma unroll
            for (int k = 0; k < 5; ++k) {
                float4 v = p[k];
                G[0][2*k]     = fmaf(d, v.x, G[0][2*k]);
                G[1][2*k]     = fmaf(d, v.y, G[1][2*k]);
                G[0][2*k + 1] = fmaf(d, v.z, G[0][2*k + 1]);
                G[1][2*k + 1] = fmaf(d, v.w, G[1][2*k + 1]);
            }
        }

        // Wait until all lanes finished last step's final matmul (Tg holds P)
        __syncwarp();
        store_cols(Tg, G, j0);
        __syncwarp();

        // G2 = G @ G ; park it in Tg2 (G register copy dies here)
        float acc[2][10];
        mm10s(Tg, G, acc);
        store_cols(Tg2, acc, j0);

        // W = B3 = a6*I + a7*G  (G regs still live here, last register use)
        float W[2][10];
#pragma unroll
        for (int j = 0; j < 2; ++j)
#pragma unroll
            for (int r = 0; r < 10; ++r)
                W[j][r] = fmaf(a7, G[j][r], (r == j0 + j) ? a6 : 0.f);
        __syncwarp();

        // Horner in G2: W = G2@W + Bi, i=2,1,0 ; no syncs inside —
        // G elementwise reads are the lane's OWN columns of Tg (program order).
#pragma unroll
        for (int it = 2; it >= 0; --it) {
            float ai = (it == 2) ? a4 : (it == 1) ? a2 : a0;
            float bi = (it == 2) ? a5 : (it == 1) ? a3 : a1;
            mm10s(Tg2, W, acc);
#pragma unroll
            for (int j = 0; j < 2; ++j) {
                const float* gc = Tg + (j0 + j) * CS;
                float4 g0 = *(const float4*)(gc);
                float4 g1 = *(const float4*)(gc + 4);
                float2 g2v = *(const float2*)(gc + 8);
                float gv[10] = {g0.x, g0.y, g0.z, g0.w, g1.x, g1.y, g1.z, g1.w, g2v.x, g2v.y};
#pragma unroll
                for (int r = 0; r < 10; ++r)
                    W[j][r] = fmaf(bi, gv[r], acc[j][r]) + ((r == j0 + j) ? ai : 0.f);
            }
        }

        // P <- P @ E : store P over the dead G tile, then matmul.
        // (Other lanes only ever read their own G columns elementwise, and all
        //  cross-lane reads of Tg happened before the sync above.)
        __syncwarp();
        store_cols(Tg, P, j0);
        __syncwarp();
        mm10s(Tg, W, acc);
#pragma unroll
        for (int j = 0; j < 2; ++j)
#pragma unroll
            for (int r = 0; r < 10; ++r) P[j][r] = acc[j][r];
    }

    if (active) {
        float* dst = g_part1 + unit * 100 + j0 * 10;
#pragma unroll
        for (int j = 0; j < 2; ++j)
#pragma unroll
            for (int r = 0; r < 10; ++r) dst[j * 10 + r] = P[j][r];
    }
}

// Combine kernel: ordered product of GRP consecutive partials (smem matmul,
// next-E prefetch). mode 0: g_part1 -> g_part2 ; mode 1: g_part2 -> out.
__global__ void __launch_bounds__(128, 5)
comb_kernel(int nUnits, int mode, float* __restrict__ out)
{
    __shared__ __align__(16) float smat[NWARP * WS];
    const float* src = (mode == 0) ? g_part1 : g_part2;
    int lane  = threadIdx.x & 31;
    int warpG = (blockIdx.x * blockDim.x + threadIdx.x) >> 5;
    int warpL = threadIdx.x >> 5;
    int g = lane / 5; if (g > 5) g = 5;
    int q = lane - g * 5; if (q > 4) q = 4;
    int unitRaw = warpG * 6 + g;
    int unit = (unitRaw < nUnits) ? unitRaw : (nUnits - 1);
    bool active = (lane < 30) && (unitRaw < nUnits);
    int j0 = q * 2;
    float* S = smat + warpL * WS + g * MS;

    const float* base = src + unit * (GRP * 100);
    float P[2][10];
#pragma unroll
    for (int j = 0; j < 2; ++j)
#pragma unroll
        for (int r = 0; r < 10; ++r)
            P[j][r] = base[(j0 + j) * 10 + r];

    float En[2][10];
#pragma unroll
    for (int j = 0; j < 2; ++j)
#pragma unroll
        for (int r = 0; r < 10; ++r)
            En[j][r] = base[100 + (j0 + j) * 10 + r];

#pragma unroll 1
    for (int e = 1; e < GRP; ++e) {
        float E[2][10];
#pragma unroll
        for (int j = 0; j < 2; ++j)
#pragma unroll
            for (int r = 0; r < 10; ++r) E[j][r] = En[j][r];
        if (e + 1 < GRP) {
            const float* nb = base + (e + 1) * 100;
#pragma unroll
            for (int j = 0; j < 2; ++j)
#pragma unroll
                for (int r = 0; r < 10; ++r)
                    En[j][r] = nb[(j0 + j) * 10 + r];
        }
        __syncwarp();
        store_cols(S, P, j0);
        __syncwarp();
        float acc[2][10];
        mm10s(S, E, acc);
#pragma unroll
        for (int j = 0; j < 2; ++j)
#pragma unroll
            for (int r = 0; r < 10; ++r) P[j][r] = acc[j][r];
    }

    if (active) {
        if (mode == 0) {
            float* dst = g_part2 + unit * 100 + j0 * 10;
#pragma unroll
            for (int j = 0; j < 2; ++j)
#pragma unroll
                for (int r = 0; r < 10; ++r) dst[j * 10 + r] = P[j][r];
        } else {
            float* dst = out + unit * 100; // unit == chain = n*C + c
#pragma unroll
            for (int j = 0; j < 2; ++j)
#pragma unroll
                for (int r = 0; r < 10; ++r) dst[r * 10 + (j0 + j)] = P[j][r];
        }
    }
}

extern "C" void kernel_launch(void* const* d_in, const int* in_sizes, int n_in,
                              void* d_out, int out_size)
{
    const float* x = (const float*)d_in[0];
    const float* A = (const float*)d_in[1];
    if (n_in >= 2 && in_sizes[0] == C_C * IN_P * M_M * M_M) { // defensive order check
        x = (const float*)d_in[1];
        A = (const float*)d_in[0];
    }
    float* out = (float*)d_out;

    // 128 threads = 4 warps = 24 units per block
    int b1 = (NU1 + 23) / 24;
    seg_kernel<<<b1, 128>>>(x, A);
    int b2 = (NU2 + 23) / 24;
    comb_kernel<<<b2, 128>>>(NU2, 0, out);
    int b3 = (NU3 + 23) / 24;
    comb_kernel<<<b3, 128>>>(NU3, 1, out);
}